// round 3
// baseline (speedup 1.0000x reference)
#include <cuda_runtime.h>
#include <cuda_bf16.h>

// Discriminator_73598559584743
// out[b, n]     = cos(s[b,n,:], h_rl[b,n,:])
// out[b, N + n] = cos(s[b,n,:], h_fk[b,n,:])
// F.normalize semantics: x / max(||x||_2, 1e-12)
// Shapes: B=8, N=8192, D=512 (fp32). Output [B, 2N] fp32.
//
// HBM-bound streaming reduction. One warp per row, 12 front-batched
// LDG.128 per lane (max MLP_p1 — measured to be the lever that moves
// DRAM%), launch_bounds(256,7) caps regs at 36 for 7 CTAs/SM.

#define D_DIM 512
#define N_DIM 8192
#define EPS 1e-12f

__global__ void __launch_bounds__(256, 7) disc_kernel(
    const float4* __restrict__ s,
    const float4* __restrict__ rl,
    const float4* __restrict__ fk,
    float* __restrict__ out,
    int n_rows)
{
    const int row  = blockIdx.x * 8 + (threadIdx.x >> 5);
    const int lane = threadIdx.x & 31;
    if (row >= n_rows) return;

    const size_t base = (size_t)row * (D_DIM / 4) + lane;  // 128 float4 per row
    const float4* sp = s  + base;
    const float4* rp = rl + base;
    const float4* fp = fk + base;

    // Front-batch all 12 loads: maximize independent LDG.128 in flight.
    float4 a0 = sp[ 0], a1 = sp[32], a2 = sp[64], a3 = sp[96];
    float4 b0 = rp[ 0], b1 = rp[32], b2 = rp[64], b3 = rp[96];
    float4 c0 = fp[ 0], c1 = fp[32], c2 = fp[64], c3 = fp[96];

    float ss = 0.f, rr = 0.f, ff = 0.f, srl = 0.f, sfk = 0.f;

#define ACC(a, b, c)                                                           \
    ss  = fmaf(a.x, a.x, fmaf(a.y, a.y, fmaf(a.z, a.z, fmaf(a.w, a.w, ss)))); \
    rr  = fmaf(b.x, b.x, fmaf(b.y, b.y, fmaf(b.z, b.z, fmaf(b.w, b.w, rr)))); \
    ff  = fmaf(c.x, c.x, fmaf(c.y, c.y, fmaf(c.z, c.z, fmaf(c.w, c.w, ff)))); \
    srl = fmaf(a.x, b.x, fmaf(a.y, b.y, fmaf(a.z, b.z, fmaf(a.w, b.w, srl)))); \
    sfk = fmaf(a.x, c.x, fmaf(a.y, c.y, fmaf(a.z, c.z, fmaf(a.w, c.w, sfk))));

    ACC(a0, b0, c0)
    ACC(a1, b1, c1)
    ACC(a2, b2, c2)
    ACC(a3, b3, c3)
#undef ACC

    // Warp tree reduction of the 5 partials.
#pragma unroll
    for (int off = 16; off > 0; off >>= 1) {
        ss  += __shfl_xor_sync(0xFFFFFFFFu, ss,  off);
        rr  += __shfl_xor_sync(0xFFFFFFFFu, rr,  off);
        ff  += __shfl_xor_sync(0xFFFFFFFFu, ff,  off);
        srl += __shfl_xor_sync(0xFFFFFFFFu, srl, off);
        sfk += __shfl_xor_sync(0xFFFFFFFFu, sfk, off);
    }

    if (lane == 0) {
        const float ns  = fmaxf(sqrtf(ss), EPS);
        const float nrl = fmaxf(sqrtf(rr), EPS);
        const float nfk = fmaxf(sqrtf(ff), EPS);
        const int b = row / N_DIM;
        const int n = row - b * N_DIM;
        float* ob = out + (size_t)b * (2 * N_DIM);
        ob[n]         = srl / (ns * nrl);
        ob[N_DIM + n] = sfk / (ns * nfk);
    }
}

extern "C" void kernel_launch(void* const* d_in, const int* in_sizes, int n_in,
                              void* d_out, int out_size)
{
    const float4* s  = (const float4*)d_in[0];
    const float4* rl = (const float4*)d_in[1];
    const float4* fk = (const float4*)d_in[2];
    float* out = (float*)d_out;

    const int n_rows = in_sizes[0] / D_DIM;   // 65536
    const int blocks = (n_rows + 7) / 8;      // one warp per row, 8 warps/CTA

    disc_kernel<<<blocks, 256>>>(s, rl, fk, out, n_rows);
}

// round 4
// speedup vs baseline: 1.0499x; 1.0499x over previous
#include <cuda_runtime.h>
#include <cuda_bf16.h>

// Discriminator_73598559584743
// out[b, n]     = cos(s[b,n,:], h_rl[b,n,:])
// out[b, N + n] = cos(s[b,n,:], h_fk[b,n,:])
// F.normalize semantics: x / max(||x||_2, 1e-12)
// Shapes: B=8, N=8192, D=512 (fp32). Output [B, 2N] fp32.
//
// HBM-bound streaming reduction. One warp per row, 12 front-batched
// LDG.128 per lane (proven best memory shape: DRAM 85.3%). No register
// cap — every reg cap destroyed the front batch. 128-thread CTAs for
// finer tail-wave granularity.

#define D_DIM 512
#define N_DIM 8192
#define EPS 1e-12f

__global__ void __launch_bounds__(128) disc_kernel(
    const float4* __restrict__ s,
    const float4* __restrict__ rl,
    const float4* __restrict__ fk,
    float* __restrict__ out,
    int n_rows)
{
    const int row  = blockIdx.x * 4 + (threadIdx.x >> 5);
    const int lane = threadIdx.x & 31;
    if (row >= n_rows) return;

    const size_t base = (size_t)row * (D_DIM / 4) + lane;  // 128 float4 per row
    const float4* sp = s  + base;
    const float4* rp = rl + base;
    const float4* fp = fk + base;

    // Front-batch all 12 loads: maximize independent LDG.128 in flight.
    float4 a0 = sp[ 0], a1 = sp[32], a2 = sp[64], a3 = sp[96];
    float4 b0 = rp[ 0], b1 = rp[32], b2 = rp[64], b3 = rp[96];
    float4 c0 = fp[ 0], c1 = fp[32], c2 = fp[64], c3 = fp[96];

    float ss = 0.f, rr = 0.f, ff = 0.f, srl = 0.f, sfk = 0.f;

#define ACC(a, b, c)                                              \
    ss  += a.x*a.x + a.y*a.y + a.z*a.z + a.w*a.w;                 \
    rr  += b.x*b.x + b.y*b.y + b.z*b.z + b.w*b.w;                 \
    ff  += c.x*c.x + c.y*c.y + c.z*c.z + c.w*c.w;                 \
    srl += a.x*b.x + a.y*b.y + a.z*b.z + a.w*b.w;                 \
    sfk += a.x*c.x + a.y*c.y + a.z*c.z + a.w*c.w;

    ACC(a0, b0, c0)
    ACC(a1, b1, c1)
    ACC(a2, b2, c2)
    ACC(a3, b3, c3)
#undef ACC

    // Warp tree reduction of the 5 partials.
#pragma unroll
    for (int off = 16; off > 0; off >>= 1) {
        ss  += __shfl_xor_sync(0xFFFFFFFFu, ss,  off);
        rr  += __shfl_xor_sync(0xFFFFFFFFu, rr,  off);
        ff  += __shfl_xor_sync(0xFFFFFFFFu, ff,  off);
        srl += __shfl_xor_sync(0xFFFFFFFFu, srl, off);
        sfk += __shfl_xor_sync(0xFFFFFFFFu, sfk, off);
    }

    if (lane == 0) {
        const float ns  = fmaxf(sqrtf(ss), EPS);
        const float nrl = fmaxf(sqrtf(rr), EPS);
        const float nfk = fmaxf(sqrtf(ff), EPS);
        const int b = row / N_DIM;
        const int n = row - b * N_DIM;
        float* ob = out + (size_t)b * (2 * N_DIM);
        ob[n]         = srl / (ns * nrl);
        ob[N_DIM + n] = sfk / (ns * nfk);
    }
}

extern "C" void kernel_launch(void* const* d_in, const int* in_sizes, int n_in,
                              void* d_out, int out_size)
{
    const float4* s  = (const float4*)d_in[0];
    const float4* rl = (const float4*)d_in[1];
    const float4* fk = (const float4*)d_in[2];
    float* out = (float*)d_out;

    const int n_rows = in_sizes[0] / D_DIM;   // 65536
    const int blocks = (n_rows + 3) / 4;      // one warp per row, 4 warps/CTA

    disc_kernel<<<blocks, 128>>>(s, rl, fk, out, n_rows);
}